// round 1
// baseline (speedup 1.0000x reference)
#include <cuda_runtime.h>
#include <math.h>

// Problem constants
#define BB 4
#define TT 8192
#define CC 128
#define RR 64       // residual channels
#define SS 256      // skip channels
#define LL 16

// Output region offsets (pytree flatten order: out, in_acts, cond)
#define OUT_OFF    0
#define OUT_SZ     (BB*256*TT)               // 8388608
#define INACT_OFF  (OUT_SZ)                  // 8388608
#define INACT_SZ   (BB*LL*128*TT)            // 67108864
#define COND_OFF   (INACT_OFF + INACT_SZ)    // 75497472

#define SQRT_HALF 0.70710678118654752440f

// Scratch (device globals; no allocation allowed)
__device__ float g_x0[BB*RR*TT];
__device__ float g_x1[BB*RR*TT];
__device__ float g_skip[BB*SS*TT];

// ---------------------------------------------------------------------------
// embed: x0[b,r,t] = embed[tokens[b,t], r]
// grid (T/256, B), 256 threads
// ---------------------------------------------------------------------------
__global__ void embed_kernel(const int* __restrict__ tokens,
                             const float* __restrict__ embed,
                             float* __restrict__ x0)
{
    __shared__ int tok[256];
    const int t0 = blockIdx.x * 256;
    const int b  = blockIdx.y;
    tok[threadIdx.x] = tokens[b*TT + t0 + threadIdx.x];
    __syncthreads();
    const int v = tok[threadIdx.x];
    #pragma unroll 4
    for (int r = 0; r < RR; r++) {
        x0[(b*RR + r)*TT + t0 + threadIdx.x] = embed[v*RR + r];
    }
}

// ---------------------------------------------------------------------------
// cond: cond[b, og, t] = sum_c cond_W[og,c]*features[b,c,t] + cond_b[og]
// writes straight into the cond region of d_out, layout [b][l][128][T]
// grid (T/64, 2048/64, B), 256 threads, dyn smem 64KB
// ---------------------------------------------------------------------------
__global__ void cond_kernel(const float* __restrict__ features,
                            const float* __restrict__ cond_W,
                            const float* __restrict__ cond_b,
                            float* __restrict__ cond_out)
{
    extern __shared__ float sm[];
    float* sF = sm;          // [c:128][t:64]
    float* sW = sm + 8192;   // [o:64][c:128]
    const int tid = threadIdx.x;
    const int t0  = blockIdx.x * 64;
    const int og0 = blockIdx.y * 64;
    const int b   = blockIdx.z;

    for (int e = tid; e < 8192; e += 256) {
        int c = e >> 6, t = e & 63;
        sF[e] = features[(b*CC + c)*TT + t0 + t];
        sW[e] = cond_W[og0*CC + e];
    }
    __syncthreads();

    const int og = tid >> 4, tg = tid & 15;
    const int oo = og * 4, tt = tg * 4;
    float acc[4][4];
    #pragma unroll
    for (int i = 0; i < 4; i++)
        #pragma unroll
        for (int j = 0; j < 4; j++) acc[i][j] = 0.f;

    #pragma unroll 4
    for (int c = 0; c < CC; c++) {
        float4 f4 = *(const float4*)(sF + (c << 6) + tt);
        float fv[4] = {f4.x, f4.y, f4.z, f4.w};
        #pragma unroll
        for (int oy = 0; oy < 4; oy++) {
            float w = sW[(oo + oy)*CC + c];
            #pragma unroll
            for (int j = 0; j < 4; j++) acc[oy][j] += w * fv[j];
        }
    }

    #pragma unroll
    for (int oy = 0; oy < 4; oy++) {
        int o_g = og0 + oo + oy;
        float bv = cond_b[o_g];
        int l = o_g >> 7, oin = o_g & 127;
        float4 r;
        r.x = acc[oy][0] + bv; r.y = acc[oy][1] + bv;
        r.z = acc[oy][2] + bv; r.w = acc[oy][3] + bv;
        *(float4*)(cond_out + (((size_t)(b*LL + l)*128 + oin)*TT) + t0 + tt) = r;
    }
}

// ---------------------------------------------------------------------------
// layer kernel: one wavenet layer over a (b, 64-t) tile
// grid (T/64, B), 512 threads, dyn smem 147456B
// ---------------------------------------------------------------------------
__global__ void layer_kernel(const float* __restrict__ x_in,
                             float* __restrict__ x_out,
                             const float* __restrict__ dilate_W,
                             const float* __restrict__ dilate_b,
                             const float* __restrict__ res_W,
                             const float* __restrict__ res_b,
                             const float* __restrict__ skip_W,
                             const float* __restrict__ skip_b,
                             const float* __restrict__ cond_g,
                             float* __restrict__ inacts_g,
                             float* __restrict__ skip_g,
                             int layer, int dil, int first, int last)
{
    extern __shared__ float sm[];
    float* sXc = sm;            // [k:64][t:64]
    float* sXp = sm + 4096;     // [k:64][t:64]
    float* sW  = sm + 8192;     // union: 20480 floats
    float* sA  = sm + 28672;    // [o:128][t:64]
    const int tid = threadIdx.x;
    const int t0  = blockIdx.x * 64;
    const int b   = blockIdx.y;

    // ---- phase A: load x tiles + dilate weights (transposed, padded rows)
    const float* xb = x_in + (size_t)b*RR*TT;
    for (int e = tid; e < 4096; e += 512) {
        int k = e >> 6, t = e & 63;
        sXc[e] = xb[k*TT + t0 + t];
        int tp = t0 + t - dil;
        sXp[e] = (tp >= 0) ? xb[k*TT + tp] : 0.f;
    }
    float* sW0 = sW;            // [k:64][o:132pad]
    float* sW1 = sW + 8448;
    const float2* dW2 = (const float2*)dilate_W + (size_t)layer*8192;
    for (int e = tid; e < 8192; e += 512) {
        int o = e >> 6, k = e & 63;
        float2 w = dW2[e];
        sW0[k*132 + o] = w.x;
        sW1[k*132 + o] = w.y;
    }
    __syncthreads();

    // ---- phase B: ia = W0 @ x_prev + W1 @ x_cur + b ; a = ia + cond
    const int og = tid >> 4, tg = tid & 15;   // 32 o-groups x 16 t-groups
    const int oo = og * 4, tt = tg * 4;
    float acc[4][4];
    #pragma unroll
    for (int i = 0; i < 4; i++)
        #pragma unroll
        for (int j = 0; j < 4; j++) acc[i][j] = 0.f;

    #pragma unroll 4
    for (int k = 0; k < 64; k++) {
        float4 xc4 = *(const float4*)(sXc + (k << 6) + tt);
        float4 xp4 = *(const float4*)(sXp + (k << 6) + tt);
        float4 w04 = *(const float4*)(sW0 + k*132 + oo);
        float4 w14 = *(const float4*)(sW1 + k*132 + oo);
        float xcv[4] = {xc4.x, xc4.y, xc4.z, xc4.w};
        float xpv[4] = {xp4.x, xp4.y, xp4.z, xp4.w};
        float w0v[4] = {w04.x, w04.y, w04.z, w04.w};
        float w1v[4] = {w14.x, w14.y, w14.z, w14.w};
        #pragma unroll
        for (int oy = 0; oy < 4; oy++)
            #pragma unroll
            for (int j = 0; j < 4; j++)
                acc[oy][j] += w0v[oy]*xpv[j] + w1v[oy]*xcv[j];
    }

    {
        const float* condp = cond_g + ((size_t)(b*LL + layer)*128)*TT + t0;
        float*       iap   = inacts_g + ((size_t)(b*LL + layer)*128)*TT + t0;
        #pragma unroll
        for (int oy = 0; oy < 4; oy++) {
            int o = oo + oy;
            float bia = dilate_b[layer*128 + o];
            float4 cv = *(const float4*)(condp + (size_t)o*TT + tt);
            float4 ia;
            ia.x = acc[oy][0] + bia; ia.y = acc[oy][1] + bia;
            ia.z = acc[oy][2] + bia; ia.w = acc[oy][3] + bia;
            *(float4*)(iap + (size_t)o*TT + tt) = ia;
            sA[(o << 6) + tt + 0] = ia.x + cv.x;
            sA[(o << 6) + tt + 1] = ia.y + cv.y;
            sA[(o << 6) + tt + 2] = ia.z + cv.z;
            sA[(o << 6) + tt + 3] = ia.w + cv.w;
        }
    }
    __syncthreads();

    // ---- load phase-C weights + gated activation (in place in sA lower half)
    const float* skW = skip_W + (size_t)layer*SS*RR;
    for (int e = tid; e < SS*RR; e += 512) sW[e] = skW[e];   // [o:256][k:64]
    if (!last) {
        const float* rW = res_W + (size_t)layer*RR*RR;
        for (int e = tid; e < RR*RR; e += 512) sW[16384 + e] = rW[e]; // [o:64][k:64]
    }
    for (int e = tid; e < 4096; e += 512) {
        float av = sA[e];
        float bv = sA[e + 4096];
        sA[e] = tanhf(av) * (1.f / (1.f + __expf(-bv)));
    }
    __syncthreads();

    // ---- phase C1: skip = skip_W @ acts + b, accumulate
    {
        const int o0 = og * 8;
        float sacc[8][4];
        #pragma unroll
        for (int i = 0; i < 8; i++)
            #pragma unroll
            for (int j = 0; j < 4; j++) sacc[i][j] = 0.f;
        #pragma unroll 2
        for (int k = 0; k < 64; k++) {
            float4 a4 = *(const float4*)(sA + (k << 6) + tt);
            float av[4] = {a4.x, a4.y, a4.z, a4.w};
            #pragma unroll
            for (int oy = 0; oy < 8; oy++) {
                float w = sW[(o0 + oy)*64 + k];
                #pragma unroll
                for (int j = 0; j < 4; j++) sacc[oy][j] += w * av[j];
            }
        }
        float* sg = skip_g + (size_t)b*SS*TT + t0;
        #pragma unroll
        for (int oy = 0; oy < 8; oy++) {
            int o = o0 + oy;
            float bv = skip_b[layer*SS + o];
            float4 r;
            r.x = sacc[oy][0] + bv; r.y = sacc[oy][1] + bv;
            r.z = sacc[oy][2] + bv; r.w = sacc[oy][3] + bv;
            float* p = sg + (size_t)o*TT + tt;
            if (!first) {
                float4 old = *(const float4*)p;
                r.x += old.x; r.y += old.y; r.z += old.z; r.w += old.w;
            }
            *(float4*)p = r;
        }
    }

    // ---- phase C2: res + residual update (skip on last layer; x unused after)
    if (!last) {
        const int o0 = og * 2;
        float racc[2][4];
        #pragma unroll
        for (int i = 0; i < 2; i++)
            #pragma unroll
            for (int j = 0; j < 4; j++) racc[i][j] = 0.f;
        #pragma unroll 4
        for (int k = 0; k < 64; k++) {
            float4 a4 = *(const float4*)(sA + (k << 6) + tt);
            float av[4] = {a4.x, a4.y, a4.z, a4.w};
            #pragma unroll
            for (int oy = 0; oy < 2; oy++) {
                float w = sW[16384 + (o0 + oy)*64 + k];
                #pragma unroll
                for (int j = 0; j < 4; j++) racc[oy][j] += w * av[j];
            }
        }
        float* xo = x_out + (size_t)b*RR*TT + t0;
        #pragma unroll
        for (int oy = 0; oy < 2; oy++) {
            int o = o0 + oy;
            float rb = res_b[layer*RR + o];
            float4 xc = *(const float4*)(sXc + (o << 6) + tt);
            float4 r;
            r.x = (racc[oy][0] + rb + xc.x) * SQRT_HALF;
            r.y = (racc[oy][1] + rb + xc.y) * SQRT_HALF;
            r.z = (racc[oy][2] + rb + xc.z) * SQRT_HALF;
            r.w = (racc[oy][3] + rb + xc.w) * SQRT_HALF;
            *(float4*)(xo + (size_t)o*TT + tt) = r;
        }
    }
}

// ---------------------------------------------------------------------------
// final head: h=relu(skip); h2=relu(Wout@h); out=Wend@h2, shifted right by 1
// grid (T/64, B), 512 threads, dyn smem 96KB
// ---------------------------------------------------------------------------
__global__ void final_kernel(const float* __restrict__ skip_g,
                             const float* __restrict__ Wout,
                             const float* __restrict__ Wend,
                             float* __restrict__ out)
{
    extern __shared__ float sm[];
    float* sH = sm;            // [k:256][t:64]
    float* sW = sm + 16384;    // [o:256][kk:32] chunk
    const int tid = threadIdx.x;
    const int t0  = blockIdx.x * 64;
    const int b   = blockIdx.y;

    for (int e = tid; e < 16384; e += 512) {
        int k = e >> 6, t = e & 63;
        float v = skip_g[((size_t)b*SS + k)*TT + t0 + t];
        sH[e] = fmaxf(v, 0.f);
    }

    const int og = tid >> 4, tg = tid & 15;
    const int oo = og * 8, tt = tg * 4;
    float acc[8][4];
    #pragma unroll
    for (int i = 0; i < 8; i++)
        #pragma unroll
        for (int j = 0; j < 4; j++) acc[i][j] = 0.f;

    for (int kc = 0; kc < 256; kc += 32) {
        __syncthreads();
        for (int e = tid; e < 8192; e += 512) {
            int o = e >> 5, kk = e & 31;
            sW[e] = Wout[o*256 + kc + kk];
        }
        __syncthreads();
        #pragma unroll 4
        for (int kk = 0; kk < 32; kk++) {
            float4 a4 = *(const float4*)(sH + ((kc + kk) << 6) + tt);
            float av[4] = {a4.x, a4.y, a4.z, a4.w};
            #pragma unroll
            for (int oy = 0; oy < 8; oy++) {
                float w = sW[(oo + oy)*32 + kk];
                #pragma unroll
                for (int j = 0; j < 4; j++) acc[oy][j] += w * av[j];
            }
        }
    }

    // h2 = relu(acc) into sH
    __syncthreads();
    #pragma unroll
    for (int oy = 0; oy < 8; oy++) {
        float4 r;
        r.x = fmaxf(acc[oy][0], 0.f); r.y = fmaxf(acc[oy][1], 0.f);
        r.z = fmaxf(acc[oy][2], 0.f); r.w = fmaxf(acc[oy][3], 0.f);
        *(float4*)(sH + ((oo + oy) << 6) + tt) = r;
    }

    float acc2[8][4];
    #pragma unroll
    for (int i = 0; i < 8; i++)
        #pragma unroll
        for (int j = 0; j < 4; j++) acc2[i][j] = 0.f;

    for (int kc = 0; kc < 256; kc += 32) {
        __syncthreads();
        for (int e = tid; e < 8192; e += 512) {
            int o = e >> 5, kk = e & 31;
            sW[e] = Wend[o*256 + kc + kk];
        }
        __syncthreads();
        #pragma unroll 4
        for (int kk = 0; kk < 32; kk++) {
            float4 a4 = *(const float4*)(sH + ((kc + kk) << 6) + tt);
            float av[4] = {a4.x, a4.y, a4.z, a4.w};
            #pragma unroll
            for (int oy = 0; oy < 8; oy++) {
                float w = sW[(oo + oy)*32 + kk];
                #pragma unroll
                for (int j = 0; j < 4; j++) acc2[oy][j] += w * av[j];
            }
        }
    }

    // shifted write: out[:, :, t+1] = val[t]; out[:, :, 0] = 0
    #pragma unroll
    for (int oy = 0; oy < 8; oy++) {
        int o = oo + oy;
        float* op = out + ((size_t)b*256 + o)*TT;
        #pragma unroll
        for (int j = 0; j < 4; j++) {
            int tg_ = t0 + tt + j + 1;
            if (tg_ < TT) op[tg_] = acc2[oy][j];
        }
    }
    if (blockIdx.x == 0 && tid < 256) out[((size_t)b*256 + tid)*TT] = 0.f;
}

// ---------------------------------------------------------------------------
extern "C" void kernel_launch(void* const* d_in, const int* in_sizes, int n_in,
                              void* d_out, int out_size)
{
    const float* features   = (const float*)d_in[0];
    const int*   tokens     = (const int*)  d_in[1];
    const float* embed      = (const float*)d_in[2];
    const float* cond_W     = (const float*)d_in[3];
    const float* cond_b     = (const float*)d_in[4];
    const float* dilate_W   = (const float*)d_in[5];
    const float* dilate_b   = (const float*)d_in[6];
    const float* res_W      = (const float*)d_in[7];
    const float* res_b      = (const float*)d_in[8];
    const float* skip_W     = (const float*)d_in[9];
    const float* skip_b     = (const float*)d_in[10];
    const float* conv_out_W = (const float*)d_in[11];
    const float* conv_end_W = (const float*)d_in[12];
    float* outp = (float*)d_out;

    float* out_r   = outp + OUT_OFF;
    float* inact_r = outp + INACT_OFF;
    float* cond_r  = outp + COND_OFF;

    float *x0, *x1, *skip;
    cudaGetSymbolAddress((void**)&x0,   g_x0);
    cudaGetSymbolAddress((void**)&x1,   g_x1);
    cudaGetSymbolAddress((void**)&skip, g_skip);

    static const int DIL[LL] = {1,2,4,8,16,32,64,128,256,1,2,4,8,16,32,64};

    cudaFuncSetAttribute(cond_kernel,  cudaFuncAttributeMaxDynamicSharedMemorySize, 65536);
    cudaFuncSetAttribute(layer_kernel, cudaFuncAttributeMaxDynamicSharedMemorySize, 147456);
    cudaFuncSetAttribute(final_kernel, cudaFuncAttributeMaxDynamicSharedMemorySize, 98304);

    embed_kernel<<<dim3(TT/256, BB), 256>>>(tokens, embed, x0);
    cond_kernel<<<dim3(TT/64, 2048/64, BB), 256, 65536>>>(features, cond_W, cond_b, cond_r);

    float* xi = x0;
    float* xo = x1;
    for (int i = 0; i < LL; i++) {
        layer_kernel<<<dim3(TT/64, BB), 512, 147456>>>(
            xi, xo, dilate_W, dilate_b, res_W, res_b, skip_W, skip_b,
            cond_r, inact_r, skip,
            i, DIL[i], (i == 0) ? 1 : 0, (i == LL-1) ? 1 : 0);
        float* t = xi; xi = xo; xo = t;
    }

    final_kernel<<<dim3(TT/64, BB), 512, 98304>>>(skip, conv_out_W, conv_end_W, out_r);
}

// round 4
// speedup vs baseline: 1.7599x; 1.7599x over previous
#include <cuda_runtime.h>
#include <cuda_fp16.h>
#include <math.h>
#include <stdint.h>

// Problem constants
#define BB 4
#define TT 8192
#define CC 128
#define RRC 64       // residual channels
#define SSC 256      // skip channels
#define LLC 16

// Output region offsets (pytree flatten order: out, in_acts, cond)
#define OUT_SZ     (BB*256*TT)
#define INACT_OFF  (OUT_SZ)
#define INACT_SZ   (BB*LLC*128*TT)
#define COND_OFF   (INACT_OFF + INACT_SZ)

#define SQRT_HALF 0.70710678118654752440f

// Scratch (device globals; no allocation allowed)
__device__ float g_x0[BB*RRC*TT];
__device__ float g_x1[BB*RRC*TT];
__device__ float g_skip[BB*SSC*TT];

// ===========================================================================
// mma.sync helpers (portable PTX: sm_80+, works on compute_103 target)
// ===========================================================================
__device__ __forceinline__ uint32_t smem_u32(const void* p) {
    uint32_t a;
    asm("{ .reg .u64 t; cvta.to.shared.u64 t, %1; cvt.u32.u64 %0, t; }" : "=r"(a) : "l"(p));
    return a;
}

__device__ __forceinline__ void ldsm4(uint32_t* r, uint32_t a) {
    asm volatile("ldmatrix.sync.aligned.m8n8.x4.shared.b16 {%0,%1,%2,%3}, [%4];"
        : "=r"(r[0]), "=r"(r[1]), "=r"(r[2]), "=r"(r[3]) : "r"(a));
}

__device__ __forceinline__ void mma16816(float* d, const uint32_t* a, const uint32_t* b) {
    asm volatile(
        "mma.sync.aligned.m16n8k16.row.col.f32.f16.f16.f32 "
        "{%0,%1,%2,%3}, {%4,%5,%6,%7}, {%8,%9}, {%0,%1,%2,%3};"
        : "+f"(d[0]), "+f"(d[1]), "+f"(d[2]), "+f"(d[3])
        : "r"(a[0]), "r"(a[1]), "r"(a[2]), "r"(a[3]), "r"(b[0]), "r"(b[1]));
}

// A fragment (m16 x k16) from row-major [m][k] smem, stride in halves
__device__ __forceinline__ void ldA(uint32_t* fr, const char* sb, int off, int stride,
                                    int m0, int k0, int lane) {
    uint32_t a = smem_u32(sb + off) +
        (uint32_t)(((m0 + (lane & 15)) * stride + k0 + ((lane >> 4) * 8)) << 1);
    ldsm4(fr, a);
}
// B fragments for TWO n8 tiles (n0..n0+15 x k16) from row-major [n][k] smem.
// regs {0,1} = b-frag for n-tile at n0, regs {2,3} = n-tile at n0+8.
__device__ __forceinline__ void ldB(uint32_t* fr, const char* sb, int off, int stride,
                                    int n0, int k0, int lane) {
    uint32_t a = smem_u32(sb + off) +
        (uint32_t)(((n0 + ((lane >> 4) & 1) * 8 + (lane & 7)) * stride
                    + k0 + ((lane >> 3) & 1) * 8) << 1);
    ldsm4(fr, a);
}

__device__ __forceinline__ void split2(float v, __half& h, __half& l) {
    h = __float2half_rn(v);
    l = __float2half_rn(v - __half2float(h));
}

// ===========================================================================
// embed: x0[b,r,t] = embed[tokens[b,t], r]
// ===========================================================================
__global__ void embed_kernel(const int* __restrict__ tokens,
                             const float* __restrict__ embed,
                             float* __restrict__ x0)
{
    __shared__ int tok[256];
    const int t0 = blockIdx.x * 256;
    const int b  = blockIdx.y;
    tok[threadIdx.x] = tokens[b*TT + t0 + threadIdx.x];
    __syncthreads();
    const int v = tok[threadIdx.x];
    #pragma unroll 4
    for (int r = 0; r < RRC; r++)
        x0[(b*RRC + r)*TT + t0 + threadIdx.x] = embed[v*RRC + r];
}

// ===========================================================================
// cond (mma fp16 3-pass): cond[b,l*128+o,t] = cond_W_block @ features + b
// grid (T/128=64, 16, B), 512 threads
// smem: WH[128][136], WL, FH[128][136], FL  (halves)
// ===========================================================================
#define CO_WH 0
#define CO_WL 34816
#define CO_FH 69632
#define CO_FL 104448
#define CO_SMEM 139264

__global__ void __launch_bounds__(512)
cond_mma_kernel(const float* __restrict__ features,
                const float* __restrict__ cond_W,
                const float* __restrict__ cond_b,
                float* __restrict__ cond_out)
{
    extern __shared__ char sb[];
    __half* WH = (__half*)(sb + CO_WH);
    __half* WL = (__half*)(sb + CO_WL);
    __half* FH = (__half*)(sb + CO_FH);
    __half* FL = (__half*)(sb + CO_FL);

    const int tid = threadIdx.x, wid = tid >> 5, lane = tid & 31;
    const int g = lane >> 2, tg = lane & 3;
    const int t0 = blockIdx.x * 128;
    const int l  = blockIdx.y;
    const int b  = blockIdx.z;

    const float* Wp = cond_W + (size_t)l * 128 * CC;
    for (int e = tid; e < 16384; e += 512) {
        int o = e >> 7, k = e & 127;
        __half h, lo; split2(Wp[e], h, lo);
        WH[o*136 + k] = h; WL[o*136 + k] = lo;
    }
    for (int e = tid; e < 16384; e += 512) {
        int t = e & 127, k = e >> 7;
        float v = features[((size_t)b*CC + k)*TT + t0 + t];
        __half h, lo; split2(v, h, lo);
        FH[t*136 + k] = h; FL[t*136 + k] = lo;
    }
    __syncthreads();

    const int mi = wid >> 2, ni = wid & 3;
    const int m0 = mi * 32, n0 = ni * 32;
    float acc[2][4][4] = {};

    for (int ks = 0; ks < 8; ks++) {
        int k0 = ks * 16;
        uint32_t ah[2][4], al[2][4];
        ldA(ah[0], sb, CO_WH, 136, m0,      k0, lane);
        ldA(ah[1], sb, CO_WH, 136, m0 + 16, k0, lane);
        ldA(al[0], sb, CO_WL, 136, m0,      k0, lane);
        ldA(al[1], sb, CO_WL, 136, m0 + 16, k0, lane);
        #pragma unroll
        for (int p = 0; p < 2; p++) {
            uint32_t bh[4], bl[4];
            ldB(bh, sb, CO_FH, 136, n0 + p*16, k0, lane);
            ldB(bl, sb, CO_FL, 136, n0 + p*16, k0, lane);
            #pragma unroll
            for (int mt = 0; mt < 2; mt++)
                #pragma unroll
                for (int q = 0; q < 2; q++) {
                    int nt = p*2 + q;
                    mma16816(acc[mt][nt], ah[mt], &bh[q*2]);
                    mma16816(acc[mt][nt], ah[mt], &bl[q*2]);
                    mma16816(acc[mt][nt], al[mt], &bh[q*2]);
                }
        }
    }

    #pragma unroll
    for (int mt = 0; mt < 2; mt++)
        #pragma unroll
        for (int r = 0; r < 2; r++) {
            int o = m0 + mt*16 + r*8 + g;
            float bias = cond_b[l*128 + o];
            float* row = cond_out + ((size_t)(b*LLC + l)*128 + o)*TT + t0;
            #pragma unroll
            for (int nt = 0; nt < 4; nt++) {
                int tc = n0 + nt*8 + 2*tg;
                float2 rv = make_float2(acc[mt][nt][r*2+0] + bias,
                                        acc[mt][nt][r*2+1] + bias);
                *(float2*)(row + tc) = rv;
            }
        }
}

// ===========================================================================
// layer (mma fp16 3-pass): full wavenet layer on a (b, 128-t) tile
// grid (T/128=64, B), 512 threads
// ===========================================================================
#define L_WDH  0
#define L_WDL  34816
#define L_XH   69632
#define L_XL   104448
#define L_ABUF 0
#define L_AH   66560
#define L_AL   84992
#define L_WSH  103424
#define L_WSL  140288
#define L_WRH  177152
#define L_WRL  186368
#define L_SMEM 195584

__global__ void __launch_bounds__(512)
layer_mma_kernel(const float* __restrict__ x_in,
                 float* __restrict__ x_out,
                 const float* __restrict__ dilate_W,
                 const float* __restrict__ dilate_b,
                 const float* __restrict__ res_W,
                 const float* __restrict__ res_b,
                 const float* __restrict__ skip_W,
                 const float* __restrict__ skip_b,
                 const float* __restrict__ cond_g,
                 float* __restrict__ inacts_g,
                 float* __restrict__ skip_g,
                 int layer, int dil, int first, int last)
{
    extern __shared__ char sb[];
    const int tid = threadIdx.x, wid = tid >> 5, lane = tid & 31;
    const int g = lane >> 2, tg = lane & 3;
    const int t0 = blockIdx.x * 128;
    const int b  = blockIdx.y;

    // ---- stage dilate weights (K: [0,64)=tap0 x_prev, [64,128)=tap1 x_cur)
    {
        __half* WDH = (__half*)(sb + L_WDH);
        __half* WDL = (__half*)(sb + L_WDL);
        const float2* dW2 = (const float2*)dilate_W + (size_t)layer * 8192;
        for (int e = tid; e < 8192; e += 512) {
            int i = e & 63, o = e >> 6;
            float2 w = dW2[e];
            __half h, lo;
            split2(w.x, h, lo); WDH[o*136 + i] = h;      WDL[o*136 + i] = lo;
            split2(w.y, h, lo); WDH[o*136 + 64 + i] = h; WDL[o*136 + 64 + i] = lo;
        }
    }
    // ---- stage X: [t][ks], ks<64 -> x[ks][t-dil], ks>=64 -> x[ks-64][t]
    {
        __half* XH = (__half*)(sb + L_XH);
        __half* XL = (__half*)(sb + L_XL);
        const float* xb = x_in + (size_t)b * RRC * TT;
        for (int e = tid; e < 16384; e += 512) {
            int t = e & 127, ks = e >> 7;
            float v;
            if (ks < 64) {
                int tp = t0 + t - dil;
                v = (tp >= 0) ? xb[ks*TT + tp] : 0.f;
            } else {
                v = xb[(ks - 64)*TT + t0 + t];
            }
            __half h, lo; split2(v, h, lo);
            XH[t*136 + ks] = h; XL[t*136 + ks] = lo;
        }
    }
    __syncthreads();

    // ---- GEMM1: ia_raw[128 o][128 t] = Wd @ Xcat (K=128), 3-pass split
    {
        const int mi = wid >> 2, ni = wid & 3;
        const int m0 = mi * 32, n0 = ni * 32;
        float acc[2][4][4] = {};

        for (int ks = 0; ks < 8; ks++) {
            int k0 = ks * 16;
            uint32_t ah[2][4], al[2][4];
            ldA(ah[0], sb, L_WDH, 136, m0,      k0, lane);
            ldA(ah[1], sb, L_WDH, 136, m0 + 16, k0, lane);
            ldA(al[0], sb, L_WDL, 136, m0,      k0, lane);
            ldA(al[1], sb, L_WDL, 136, m0 + 16, k0, lane);
            #pragma unroll
            for (int p = 0; p < 2; p++) {
                uint32_t bh[4], bl[4];
                ldB(bh, sb, L_XH, 136, n0 + p*16, k0, lane);
                ldB(bl, sb, L_XL, 136, n0 + p*16, k0, lane);
                #pragma unroll
                for (int mt = 0; mt < 2; mt++)
                    #pragma unroll
                    for (int q = 0; q < 2; q++) {
                        int nt = p*2 + q;
                        mma16816(acc[mt][nt], ah[mt], &bh[q*2]);
                        mma16816(acc[mt][nt], ah[mt], &bl[q*2]);
                        mma16816(acc[mt][nt], al[mt], &bh[q*2]);
                    }
            }
        }
        __syncthreads();   // all reads of WD/X done before abuf aliases them

        // epilogue1: ia = acc + bias -> gmem in_acts; a = ia + cond -> abuf
        float* abuf = (float*)(sb + L_ABUF);   // [o][stride 130] fp32
        #pragma unroll
        for (int mt = 0; mt < 2; mt++)
            #pragma unroll
            for (int r = 0; r < 2; r++) {
                int o = m0 + mt*16 + r*8 + g;
                float bias = dilate_b[layer*128 + o];
                size_t rowoff = ((size_t)(b*LLC + layer)*128 + o)*TT + t0;
                float*       iap = inacts_g + rowoff;
                const float* cp  = cond_g + rowoff;
                float* ab = abuf + o*130;
                #pragma unroll
                for (int nt = 0; nt < 4; nt++) {
                    int tc = n0 + nt*8 + 2*tg;
                    float ia0 = acc[mt][nt][r*2+0] + bias;
                    float ia1 = acc[mt][nt][r*2+1] + bias;
                    *(float2*)(iap + tc) = make_float2(ia0, ia1);
                    float2 cv = *(const float2*)(cp + tc);
                    *(float2*)(ab + tc) = make_float2(ia0 + cv.x, ia1 + cv.y);
                }
            }
    }
    __syncthreads();

    // ---- gated activation -> AH/AL; stage skip/res weights (hi/lo)
    {
        float* abuf = (float*)(sb + L_ABUF);
        __half* AH = (__half*)(sb + L_AH);   // [t][72]
        __half* AL = (__half*)(sb + L_AL);
        for (int e = tid; e < 8192; e += 512) {
            int t = e & 127, kk = e >> 7;
            float a0 = abuf[kk*130 + t];
            float a1 = abuf[(kk + 64)*130 + t];
            float act = tanhf(a0) * (1.f / (1.f + __expf(-a1)));
            __half h, lo; split2(act, h, lo);
            AH[t*72 + kk] = h; AL[t*72 + kk] = lo;
        }
        __half* WSH = (__half*)(sb + L_WSH);  // [256][72]
        __half* WSL = (__half*)(sb + L_WSL);
        const float* sWp = skip_W + (size_t)layer * SSC * RRC;
        for (int e = tid; e < 16384; e += 512) {
            int k = e & 63, o = e >> 6;
            __half h, lo; split2(sWp[e], h, lo);
            WSH[o*72 + k] = h; WSL[o*72 + k] = lo;
        }
        if (!last) {
            __half* WRH = (__half*)(sb + L_WRH);  // [64][72]
            __half* WRL = (__half*)(sb + L_WRL);
            const float* rWp = res_W + (size_t)layer * RRC * RRC;
            for (int e = tid; e < 4096; e += 512) {
                int k = e & 63, o = e >> 6;
                __half h, lo; split2(rWp[e], h, lo);
                WRH[o*72 + k] = h; WRL[o*72 + k] = lo;
            }
        }
    }
    __syncthreads();

    // ---- GEMM2: skip[256 o][128 t] = Ws @ acts (K=64), 3-pass
    {
        const int mi = wid >> 1, ni = wid & 1;
        const int m0 = mi * 32, n0 = ni * 64;
        float acc[2][8][4] = {};

        for (int ks = 0; ks < 4; ks++) {
            int k0 = ks * 16;
            uint32_t ah[2][4], al[2][4];
            ldA(ah[0], sb, L_WSH, 72, m0,      k0, lane);
            ldA(ah[1], sb, L_WSH, 72, m0 + 16, k0, lane);
            ldA(al[0], sb, L_WSL, 72, m0,      k0, lane);
            ldA(al[1], sb, L_WSL, 72, m0 + 16, k0, lane);
            #pragma unroll
            for (int p = 0; p < 4; p++) {
                uint32_t bh[4], bl[4];
                ldB(bh, sb, L_AH, 72, n0 + p*16, k0, lane);
                ldB(bl, sb, L_AL, 72, n0 + p*16, k0, lane);
                #pragma unroll
                for (int mt = 0; mt < 2; mt++)
                    #pragma unroll
                    for (int q = 0; q < 2; q++) {
                        int nt = p*2 + q;
                        mma16816(acc[mt][nt], ah[mt], &bh[q*2]);
                        mma16816(acc[mt][nt], ah[mt], &bl[q*2]);
                        mma16816(acc[mt][nt], al[mt], &bh[q*2]);
                    }
            }
        }
        #pragma unroll
        for (int mt = 0; mt < 2; mt++)
            #pragma unroll
            for (int r = 0; r < 2; r++) {
                int o = m0 + mt*16 + r*8 + g;
                float bv = skip_b[layer*SSC + o];
                float* p = skip_g + ((size_t)b*SSC + o)*TT + t0;
                #pragma unroll
                for (int nt = 0; nt < 8; nt++) {
                    int tc = n0 + nt*8 + 2*tg;
                    float2 rv = make_float2(acc[mt][nt][r*2+0] + bv,
                                            acc[mt][nt][r*2+1] + bv);
                    if (!first) {
                        float2 old = *(const float2*)(p + tc);
                        rv.x += old.x; rv.y += old.y;
                    }
                    *(float2*)(p + tc) = rv;
                }
            }
    }

    // ---- GEMM3: res[64 o][128 t] = Wr @ acts (K=64), 3-pass; x update
    if (!last) {
        const int mi = wid >> 3, ni = wid & 7;
        const int m0 = mi * 32, n0 = ni * 16;
        float acc[2][2][4] = {};

        for (int ks = 0; ks < 4; ks++) {
            int k0 = ks * 16;
            uint32_t ah[2][4], al[2][4], bh[4], bl[4];
            ldA(ah[0], sb, L_WRH, 72, m0,      k0, lane);
            ldA(ah[1], sb, L_WRH, 72, m0 + 16, k0, lane);
            ldA(al[0], sb, L_WRL, 72, m0,      k0, lane);
            ldA(al[1], sb, L_WRL, 72, m0 + 16, k0, lane);
            ldB(bh, sb, L_AH, 72, n0, k0, lane);
            ldB(bl, sb, L_AL, 72, n0, k0, lane);
            #pragma unroll
            for (int mt = 0; mt < 2; mt++)
                #pragma unroll
                for (int q = 0; q < 2; q++) {
                    mma16816(acc[mt][q], ah[mt], &bh[q*2]);
                    mma16816(acc[mt][q], ah[mt], &bl[q*2]);
                    mma16816(acc[mt][q], al[mt], &bh[q*2]);
                }
        }
        #pragma unroll
        for (int mt = 0; mt < 2; mt++)
            #pragma unroll
            for (int r = 0; r < 2; r++) {
                int o = m0 + mt*16 + r*8 + g;
                float rb = res_b[layer*RRC + o];
                const float* xi = x_in  + ((size_t)b*RRC + o)*TT + t0;
                float*       xo = x_out + ((size_t)b*RRC + o)*TT + t0;
                #pragma unroll
                for (int nt = 0; nt < 2; nt++) {
                    int tc = n0 + nt*8 + 2*tg;
                    float2 xv = *(const float2*)(xi + tc);
                    float2 rv;
                    rv.x = (acc[mt][nt][r*2+0] + rb + xv.x) * SQRT_HALF;
                    rv.y = (acc[mt][nt][r*2+1] + rb + xv.y) * SQRT_HALF;
                    *(float2*)(xo + tc) = rv;
                }
            }
    }
}

// ===========================================================================
// final head (mma fp16 single-pass):
// h=relu(skip); h2=relu(Wout@h); out=Wend@h2 (shifted right by 1)
// grid (T/128=64, B), 512 threads
// smem: W chunk [256][136] halves = 69632; H [128 t][264] halves = 67584
// ===========================================================================
#define F_W 0
#define F_H 69632
#define F_SMEM 137216

__global__ void __launch_bounds__(512)
final_mma_kernel(const float* __restrict__ skip_g,
                 const float* __restrict__ Wout,
                 const float* __restrict__ Wend,
                 float* __restrict__ out)
{
    extern __shared__ char sb[];
    __half* W = (__half*)(sb + F_W);
    __half* H = (__half*)(sb + F_H);
    const int tid = threadIdx.x, wid = tid >> 5, lane = tid & 31;
    const int g = lane >> 2, tg = lane & 3;
    const int t0 = blockIdx.x * 128;
    const int b  = blockIdx.y;

    // stage H = relu(skip)  [t][k:256]
    for (int e = tid; e < 32768; e += 512) {
        int t = e & 127, k = e >> 7;
        float v = skip_g[((size_t)b*SSC + k)*TT + t0 + t];
        H[t*264 + k] = __float2half_rn(fmaxf(v, 0.f));
    }

    const int mi = wid >> 1, ni = wid & 1;
    const int m0 = mi * 32, n0 = ni * 64;

    // ---- GEMM A: h2 = Wout @ h  (M=256, N=128, K=256 in 2 chunks)
    float acc[2][8][4] = {};
    for (int kc = 0; kc < 2; kc++) {
        __syncthreads();
        for (int e = tid; e < 32768; e += 512) {
            int o = e >> 7, kk = e & 127;
            W[o*136 + kk] = __float2half_rn(Wout[o*256 + kc*128 + kk]);
        }
        __syncthreads();
        for (int ks = 0; ks < 8; ks++) {
            int k0 = ks * 16;
            uint32_t ah[2][4];
            ldA(ah[0], sb, F_W, 136, m0,      k0, lane);
            ldA(ah[1], sb, F_W, 136, m0 + 16, k0, lane);
            #pragma unroll
            for (int p = 0; p < 4; p++) {
                uint32_t bh[4];
                ldB(bh, sb, F_H, 264, n0 + p*16, kc*128 + k0, lane);
                #pragma unroll
                for (int mt = 0; mt < 2; mt++)
                    #pragma unroll
                    for (int q = 0; q < 2; q++)
                        mma16816(acc[mt][p*2+q], ah[mt], &bh[q*2]);
            }
        }
    }
    __syncthreads();

    // h2 = relu(acc) written back into H  [t][k=o]
    #pragma unroll
    for (int mt = 0; mt < 2; mt++)
        #pragma unroll
        for (int r = 0; r < 2; r++) {
            int o = m0 + mt*16 + r*8 + g;
            #pragma unroll
            for (int nt = 0; nt < 8; nt++) {
                int tc = n0 + nt*8 + 2*tg;
                H[tc*264 + o]       = __float2half_rn(fmaxf(acc[mt][nt][r*2+0], 0.f));
                H[(tc + 1)*264 + o] = __float2half_rn(fmaxf(acc[mt][nt][r*2+1], 0.f));
            }
        }
    __syncthreads();

    // ---- GEMM B: out = Wend @ h2
    float acc2[2][8][4] = {};
    for (int kc = 0; kc < 2; kc++) {
        __syncthreads();
        for (int e = tid; e < 32768; e += 512) {
            int o = e >> 7, kk = e & 127;
            W[o*136 + kk] = __float2half_rn(Wend[o*256 + kc*128 + kk]);
        }
        __syncthreads();
        for (int ks = 0; ks < 8; ks++) {
            int k0 = ks * 16;
            uint32_t ah[2][4];
            ldA(ah[0], sb, F_W, 136, m0,      k0, lane);
            ldA(ah[1], sb, F_W, 136, m0 + 16, k0, lane);
            #pragma unroll
            for (int p = 0; p < 4; p++) {
                uint32_t bh[4];
                ldB(bh, sb, F_H, 264, n0 + p*16, kc*128 + k0, lane);
                #pragma unroll
                for (int mt = 0; mt < 2; mt++)
                    #pragma unroll
                    for (int q = 0; q < 2; q++)
                        mma16816(acc2[mt][p*2+q], ah[mt], &bh[q*2]);
            }
        }
    }

    // shifted write: out[b][o][t+1] = val[t]
    #pragma unroll
    for (int mt = 0; mt < 2; mt++)
        #pragma unroll
        for (int r = 0; r < 2; r++) {
            int o = m0 + mt*16 + r*8 + g;
            float* op = out + ((size_t)b*256 + o)*TT;
            #pragma unroll
            for (int nt = 0; nt < 8; nt++) {
                int tc = t0 + n0 + nt*8 + 2*tg;
                if (tc + 1 < TT) op[tc + 1] = acc2[mt][nt][r*2+0];
                if (tc + 2 < TT) op[tc + 2] = acc2[mt][nt][r*2+1];
            }
        }
    if (blockIdx.x == 0 && tid < 256) out[((size_t)b*256 + tid)*TT] = 0.f;
}

// ===========================================================================
extern "C" void kernel_launch(void* const* d_in, const int* in_sizes, int n_in,
                              void* d_out, int out_size)
{
    const float* features   = (const float*)d_in[0];
    const int*   tokens     = (const int*)  d_in[1];
    const float* embed      = (const float*)d_in[2];
    const float* cond_W     = (const float*)d_in[3];
    const float* cond_b     = (const float*)d_in[4];
    const float* dilate_W   = (const float*)d_in[5];
    const float* dilate_b   = (const float*)d_in[6];
    const float* res_W      = (const float*)d_in[7];
    const float* res_b      = (const float*)d_in[8];
    const float* skip_W     = (const float*)d_in[9];
    const float* skip_b     = (const float*)d_in[10];
    const float* conv_out_W = (const float*)d_in[11];
    const float* conv_end_W = (const float*)d_in[12];
    float* outp = (float*)d_out;

    float* out_r   = outp;
    float* inact_r = outp + INACT_OFF;
    float* cond_r  = outp + COND_OFF;

    float *x0, *x1, *skip;
    cudaGetSymbolAddress((void**)&x0,   g_x0);
    cudaGetSymbolAddress((void**)&x1,   g_x1);
    cudaGetSymbolAddress((void**)&skip, g_skip);

    static const int DIL[LLC] = {1,2,4,8,16,32,64,128,256,1,2,4,8,16,32,64};

    cudaFuncSetAttribute(cond_mma_kernel,  cudaFuncAttributeMaxDynamicSharedMemorySize, CO_SMEM);
    cudaFuncSetAttribute(layer_mma_kernel, cudaFuncAttributeMaxDynamicSharedMemorySize, L_SMEM);
    cudaFuncSetAttribute(final_mma_kernel, cudaFuncAttributeMaxDynamicSharedMemorySize, F_SMEM);

    embed_kernel<<<dim3(TT/256, BB), 256>>>(tokens, embed, x0);
    cond_mma_kernel<<<dim3(TT/128, LLC, BB), 512, CO_SMEM>>>(features, cond_W, cond_b, cond_r);

    float* xi = x0;
    float* xo = x1;
    for (int i = 0; i < LLC; i++) {
        layer_mma_kernel<<<dim3(TT/128, BB), 512, L_SMEM>>>(
            xi, xo, dilate_W, dilate_b, res_W, res_b, skip_W, skip_b,
            cond_r, inact_r, skip,
            i, DIL[i], (i == 0) ? 1 : 0, (i == LLC-1) ? 1 : 0);
        float* t = xi; xi = xo; xo = t;
    }

    final_mma_kernel<<<dim3(TT/128, BB), 512, F_SMEM>>>(skip, conv_out_W, conv_end_W, out_r);
}

// round 5
// speedup vs baseline: 2.0261x; 1.1513x over previous
#include <cuda_runtime.h>
#include <cuda_fp16.h>
#include <math.h>
#include <stdint.h>

// Problem constants
#define BB 4
#define TT 8192
#define CC 128
#define RRC 64       // residual channels
#define SSC 256      // skip channels
#define LLC 16

// Output region offsets (pytree flatten order: out, in_acts, cond)
#define OUT_SZ     (BB*256*TT)
#define INACT_OFF  (OUT_SZ)
#define INACT_SZ   (BB*LLC*128*TT)
#define COND_OFF   (INACT_OFF + INACT_SZ)

#define SQRT_HALF 0.70710678118654752440f

// Scratch (device globals; no allocation allowed)
__device__ float g_x0[BB*RRC*TT];
__device__ float g_x1[BB*RRC*TT];
__device__ float g_skip[BB*SSC*TT];

// Pre-packed A-operand fragments (fp16 hi/lo), mma.m16n8k16 layout.
// dilate: per layer 8 mtiles x 8 ksteps x 32 lanes -> 2048 uint4
// skip:   per layer 16 mtiles x 4 ksteps x 32 lanes -> 2048 uint4
// res:    per layer (15 used) 4 mtiles x 4 ksteps x 32 lanes -> 512 uint4
__device__ uint4 g_wd_h[LLC*2048];
__device__ uint4 g_wd_l[LLC*2048];
__device__ uint4 g_ws_h[LLC*2048];
__device__ uint4 g_ws_l[LLC*2048];
__device__ uint4 g_wr_h[15*512];
__device__ uint4 g_wr_l[15*512];

// ===========================================================================
// helpers
// ===========================================================================
__device__ __forceinline__ uint32_t smem_u32(const void* p) {
    uint32_t a;
    asm("{ .reg .u64 t; cvta.to.shared.u64 t, %1; cvt.u32.u64 %0, t; }" : "=r"(a) : "l"(p));
    return a;
}
__device__ __forceinline__ void ldsm4(uint32_t* r, uint32_t a) {
    asm volatile("ldmatrix.sync.aligned.m8n8.x4.shared.b16 {%0,%1,%2,%3}, [%4];"
        : "=r"(r[0]), "=r"(r[1]), "=r"(r[2]), "=r"(r[3]) : "r"(a));
}
__device__ __forceinline__ void mma16816(float* d, const uint32_t* a, const uint32_t* b) {
    asm volatile(
        "mma.sync.aligned.m16n8k16.row.col.f32.f16.f16.f32 "
        "{%0,%1,%2,%3}, {%4,%5,%6,%7}, {%8,%9}, {%0,%1,%2,%3};"
        : "+f"(d[0]), "+f"(d[1]), "+f"(d[2]), "+f"(d[3])
        : "r"(a[0]), "r"(a[1]), "r"(a[2]), "r"(a[3]), "r"(b[0]), "r"(b[1]));
}
// A fragment (m16 x k16) from row-major [m][k] smem (used by cond/final)
__device__ __forceinline__ void ldA(uint32_t* fr, const char* sb, int off, int stride,
                                    int m0, int k0, int lane) {
    uint32_t a = smem_u32(sb + off) +
        (uint32_t)(((m0 + (lane & 15)) * stride + k0 + ((lane >> 4) * 8)) << 1);
    ldsm4(fr, a);
}
// B fragments for TWO n8 tiles from row-major [n][k] smem
__device__ __forceinline__ void ldB(uint32_t* fr, const char* sb, int off, int stride,
                                    int n0, int k0, int lane) {
    uint32_t a = smem_u32(sb + off) +
        (uint32_t)(((n0 + ((lane >> 4) & 1) * 8 + (lane & 7)) * stride
                    + k0 + ((lane >> 3) & 1) * 8) << 1);
    ldsm4(fr, a);
}
__device__ __forceinline__ void split2(float v, __half& h, __half& l) {
    h = __float2half_rn(v);
    l = __float2half_rn(v - __half2float(h));
}
__device__ __forceinline__ uint32_t packh2(__half a, __half b) {
    __half2 h = __halves2half2(a, b);
    return *(uint32_t*)&h;
}

// ===========================================================================
// weight pre-pack kernels
// lane element map for one m16k16 frag: r=mrow+(l>>2), c=kbase+(l&3)*2
// reg0={A[r][c],A[r][c+1]}, reg1={A[r+8][c],A[r+8][c+1]},
// reg2={A[r][c+8],A[r][c+9]}, reg3={A[r+8][c+8],A[r+8][c+9]}
// ===========================================================================
__device__ __forceinline__ void pack8(const float* v, uint4& hi, uint4& lo) {
    __half eh[8], el[8];
    #pragma unroll
    for (int i = 0; i < 8; i++) split2(v[i], eh[i], el[i]);
    hi.x = packh2(eh[0], eh[1]); hi.y = packh2(eh[2], eh[3]);
    hi.z = packh2(eh[4], eh[5]); hi.w = packh2(eh[6], eh[7]);
    lo.x = packh2(el[0], el[1]); lo.y = packh2(el[2], el[3]);
    lo.z = packh2(el[4], el[5]); lo.w = packh2(el[6], el[7]);
}

__global__ void pack_dilate(const float* __restrict__ dilate_W,
                            uint4* __restrict__ outh, uint4* __restrict__ outl)
{
    int idx = blockIdx.x * 256 + threadIdx.x;   // 16*8*8*32 = 32768
    int lane = idx & 31, fi = idx >> 5;
    int ks = fi & 7, mt = (fi >> 3) & 7, l = fi >> 6;
    int r = mt*16 + (lane >> 2), cb = ks*16 + (lane & 3)*2;
    int dr[8] = {0,0,8,8,0,0,8,8};
    int dc[8] = {0,1,0,1,8,9,8,9};
    float v[8];
    #pragma unroll
    for (int i = 0; i < 8; i++) {
        int row = r + dr[i], col = cb + dc[i];
        v[i] = (col < 64)
            ? dilate_W[((l*128 + row)*64 + col)*2 + 0]
            : dilate_W[((l*128 + row)*64 + (col - 64))*2 + 1];
    }
    uint4 hi, lo; pack8(v, hi, lo);
    outh[idx] = hi; outl[idx] = lo;
}

__global__ void pack_skip(const float* __restrict__ skip_W,
                          uint4* __restrict__ outh, uint4* __restrict__ outl)
{
    int idx = blockIdx.x * 256 + threadIdx.x;   // 16*16*4*32 = 32768
    int lane = idx & 31, fi = idx >> 5;
    int ks = fi & 3, mt = (fi >> 2) & 15, l = fi >> 6;
    int r = mt*16 + (lane >> 2), cb = ks*16 + (lane & 3)*2;
    int dr[8] = {0,0,8,8,0,0,8,8};
    int dc[8] = {0,1,0,1,8,9,8,9};
    float v[8];
    #pragma unroll
    for (int i = 0; i < 8; i++)
        v[i] = skip_W[((size_t)l*256 + r + dr[i])*64 + cb + dc[i]];
    uint4 hi, lo; pack8(v, hi, lo);
    outh[idx] = hi; outl[idx] = lo;
}

__global__ void pack_res(const float* __restrict__ res_W,
                         uint4* __restrict__ outh, uint4* __restrict__ outl)
{
    int idx = blockIdx.x * 256 + threadIdx.x;   // 15*4*4*32 = 7680
    if (idx >= 7680) return;
    int lane = idx & 31, fi = idx >> 5;
    int ks = fi & 3, mt = (fi >> 2) & 3, l = fi >> 4;
    int r = mt*16 + (lane >> 2), cb = ks*16 + (lane & 3)*2;
    int dr[8] = {0,0,8,8,0,0,8,8};
    int dc[8] = {0,1,0,1,8,9,8,9};
    float v[8];
    #pragma unroll
    for (int i = 0; i < 8; i++)
        v[i] = res_W[((size_t)l*64 + r + dr[i])*64 + cb + dc[i]];
    uint4 hi, lo; pack8(v, hi, lo);
    outh[idx] = hi; outl[idx] = lo;
}

// ===========================================================================
// embed
// ===========================================================================
__global__ void embed_kernel(const int* __restrict__ tokens,
                             const float* __restrict__ embed,
                             float* __restrict__ x0)
{
    __shared__ int tok[256];
    const int t0 = blockIdx.x * 256;
    const int b  = blockIdx.y;
    tok[threadIdx.x] = tokens[b*TT + t0 + threadIdx.x];
    __syncthreads();
    const int v = tok[threadIdx.x];
    #pragma unroll 4
    for (int r = 0; r < RRC; r++)
        x0[(b*RRC + r)*TT + t0 + threadIdx.x] = embed[v*RRC + r];
}

// ===========================================================================
// cond (unchanged from R4)
// ===========================================================================
#define CO_WH 0
#define CO_WL 34816
#define CO_FH 69632
#define CO_FL 104448
#define CO_SMEM 139264

__global__ void __launch_bounds__(512)
cond_mma_kernel(const float* __restrict__ features,
                const float* __restrict__ cond_W,
                const float* __restrict__ cond_b,
                float* __restrict__ cond_out)
{
    extern __shared__ char sb[];
    __half* WH = (__half*)(sb + CO_WH);
    __half* WL = (__half*)(sb + CO_WL);
    __half* FH = (__half*)(sb + CO_FH);
    __half* FL = (__half*)(sb + CO_FL);

    const int tid = threadIdx.x, wid = tid >> 5, lane = tid & 31;
    const int g = lane >> 2, tg = lane & 3;
    const int t0 = blockIdx.x * 128;
    const int l  = blockIdx.y;
    const int b  = blockIdx.z;

    const float* Wp = cond_W + (size_t)l * 128 * CC;
    for (int e = tid; e < 16384; e += 512) {
        int o = e >> 7, k = e & 127;
        __half h, lo; split2(Wp[e], h, lo);
        WH[o*136 + k] = h; WL[o*136 + k] = lo;
    }
    for (int e = tid; e < 16384; e += 512) {
        int t = e & 127, k = e >> 7;
        float v = features[((size_t)b*CC + k)*TT + t0 + t];
        __half h, lo; split2(v, h, lo);
        FH[t*136 + k] = h; FL[t*136 + k] = lo;
    }
    __syncthreads();

    const int mi = wid >> 2, ni = wid & 3;
    const int m0 = mi * 32, n0 = ni * 32;
    float acc[2][4][4] = {};

    for (int ks = 0; ks < 8; ks++) {
        int k0 = ks * 16;
        uint32_t ah[2][4], al[2][4];
        ldA(ah[0], sb, CO_WH, 136, m0,      k0, lane);
        ldA(ah[1], sb, CO_WH, 136, m0 + 16, k0, lane);
        ldA(al[0], sb, CO_WL, 136, m0,      k0, lane);
        ldA(al[1], sb, CO_WL, 136, m0 + 16, k0, lane);
        #pragma unroll
        for (int p = 0; p < 2; p++) {
            uint32_t bh[4], bl[4];
            ldB(bh, sb, CO_FH, 136, n0 + p*16, k0, lane);
            ldB(bl, sb, CO_FL, 136, n0 + p*16, k0, lane);
            #pragma unroll
            for (int mt = 0; mt < 2; mt++)
                #pragma unroll
                for (int q = 0; q < 2; q++) {
                    int nt = p*2 + q;
                    mma16816(acc[mt][nt], ah[mt], &bh[q*2]);
                    mma16816(acc[mt][nt], ah[mt], &bl[q*2]);
                    mma16816(acc[mt][nt], al[mt], &bh[q*2]);
                }
        }
    }

    #pragma unroll
    for (int mt = 0; mt < 2; mt++)
        #pragma unroll
        for (int r = 0; r < 2; r++) {
            int o = m0 + mt*16 + r*8 + g;
            float bias = cond_b[l*128 + o];
            float* row = cond_out + ((size_t)(b*LLC + l)*128 + o)*TT + t0;
            #pragma unroll
            for (int nt = 0; nt < 4; nt++) {
                int tc = n0 + nt*8 + 2*tg;
                float2 rv = make_float2(acc[mt][nt][r*2+0] + bias,
                                        acc[mt][nt][r*2+1] + bias);
                *(float2*)(row + tc) = rv;
            }
        }
}

// ===========================================================================
// layer v2: 256 threads, t-tile 64, weights from pre-packed gmem frags
// grid (T/64=128, B), 3 CTAs/SM target
// smem: phase1 XH[64][136]+XL = 34816
//       phase2 abuf fp32[128][66]=33792, AH[64][72]+AL @33792 = 18432
// ===========================================================================
#define L2_XH   0
#define L2_XL   17408
#define L2_ABUF 0
#define L2_AH   33792
#define L2_AL   43008
#define L2_SMEM 52224

__global__ void __launch_bounds__(256, 3)
layer_mma2_kernel(const float* __restrict__ x_in,
                  float* __restrict__ x_out,
                  const uint4* __restrict__ wd_h, const uint4* __restrict__ wd_l,
                  const float* __restrict__ dilate_b,
                  const uint4* __restrict__ wr_h, const uint4* __restrict__ wr_l,
                  const float* __restrict__ res_b,
                  const uint4* __restrict__ ws_h, const uint4* __restrict__ ws_l,
                  const float* __restrict__ skip_b,
                  const float* __restrict__ cond_g,
                  float* __restrict__ inacts_g,
                  float* __restrict__ skip_g,
                  int layer, int dil, int first, int last)
{
    extern __shared__ char sb[];
    const int tid = threadIdx.x, wid = tid >> 5, lane = tid & 31;
    const int g = lane >> 2, tg = lane & 3;
    const int t0 = blockIdx.x * 64;
    const int b  = blockIdx.y;

    // ---- stage X halves: [t][ks] ks<64 -> x[ks][t-dil], else x[ks-64][t]
    {
        __half* XH = (__half*)(sb + L2_XH);
        __half* XL = (__half*)(sb + L2_XL);
        const float* xb = x_in + (size_t)b * RRC * TT;
        for (int e = tid; e < 8192; e += 256) {
            int t = e & 63, ks = e >> 6;
            float v;
            if (ks < 64) {
                int tp = t0 + t - dil;
                v = (tp >= 0) ? xb[ks*TT + tp] : 0.f;
            } else {
                v = xb[(ks - 64)*TT + t0 + t];
            }
            __half h, lo; split2(v, h, lo);
            XH[t*136 + ks] = h; XL[t*136 + ks] = lo;
        }
    }
    __syncthreads();

    const int mi = wid >> 1, ni = wid & 1;
    const int m0 = mi * 32, n0 = ni * 32;

    // ---- GEMM1: ia[128 o][64 t] = Wd @ Xcat (K=128), 3-pass
    float acc[2][4][4] = {};
    {
        const uint4* ph = wd_h + (size_t)layer * 2048;
        const uint4* pl = wd_l + (size_t)layer * 2048;
        for (int ks = 0; ks < 8; ks++) {
            uint4 A0h = ph[((mi*2    )*8 + ks)*32 + lane];
            uint4 A1h = ph[((mi*2 + 1)*8 + ks)*32 + lane];
            uint4 A0l = pl[((mi*2    )*8 + ks)*32 + lane];
            uint4 A1l = pl[((mi*2 + 1)*8 + ks)*32 + lane];
            #pragma unroll
            for (int p = 0; p < 2; p++) {
                uint32_t bh[4], bl[4];
                ldB(bh, sb, L2_XH, 136, n0 + p*16, ks*16, lane);
                ldB(bl, sb, L2_XL, 136, n0 + p*16, ks*16, lane);
                #pragma unroll
                for (int q = 0; q < 2; q++) {
                    int nt = p*2 + q;
                    mma16816(acc[0][nt], (const uint32_t*)&A0h, &bh[q*2]);
                    mma16816(acc[0][nt], (const uint32_t*)&A0h, &bl[q*2]);
                    mma16816(acc[0][nt], (const uint32_t*)&A0l, &bh[q*2]);
                    mma16816(acc[1][nt], (const uint32_t*)&A1h, &bh[q*2]);
                    mma16816(acc[1][nt], (const uint32_t*)&A1h, &bl[q*2]);
                    mma16816(acc[1][nt], (const uint32_t*)&A1l, &bh[q*2]);
                }
            }
        }
    }
    __syncthreads();   // all X reads done before abuf aliases X

    // ---- epilogue1: ia -> gmem in_acts; a = ia + cond -> abuf
    {
        float* abuf = (float*)(sb + L2_ABUF);
        #pragma unroll
        for (int mt = 0; mt < 2; mt++)
            #pragma unroll
            for (int r = 0; r < 2; r++) {
                int o = m0 + mt*16 + r*8 + g;
                float bias = dilate_b[layer*128 + o];
                size_t rowoff = ((size_t)(b*LLC + layer)*128 + o)*TT + t0;
                float*       iap = inacts_g + rowoff;
                const float* cp  = cond_g + rowoff;
                float* ab = abuf + o*66;
                #pragma unroll
                for (int nt = 0; nt < 4; nt++) {
                    int tc = n0 + nt*8 + 2*tg;
                    float ia0 = acc[mt][nt][r*2+0] + bias;
                    float ia1 = acc[mt][nt][r*2+1] + bias;
                    *(float2*)(iap + tc) = make_float2(ia0, ia1);
                    float2 cv = *(const float2*)(cp + tc);
                    *(float2*)(ab + tc) = make_float2(ia0 + cv.x, ia1 + cv.y);
                }
            }
    }
    __syncthreads();

    // ---- gated activation -> AH/AL
    {
        float* abuf = (float*)(sb + L2_ABUF);
        __half* AH = (__half*)(sb + L2_AH);
        __half* AL = (__half*)(sb + L2_AL);
        for (int e = tid; e < 4096; e += 256) {
            int t = e & 63, kk = e >> 6;
            float a0 = abuf[kk*66 + t];
            float a1 = abuf[(kk + 64)*66 + t];
            float act = tanhf(a0) * (1.f / (1.f + __expf(-a1)));
            __half h, lo; split2(act, h, lo);
            AH[t*72 + kk] = h; AL[t*72 + kk] = lo;
        }
    }
    __syncthreads();

    // ---- GEMM2: skip in two M=128 halves (K=64), 3-pass
    {
        const uint4* ph = ws_h + (size_t)layer * 2048;
        const uint4* pl = ws_l + (size_t)layer * 2048;
        #pragma unroll
        for (int h = 0; h < 2; h++) {
            float acc2[2][4][4] = {};
            for (int ks = 0; ks < 4; ks++) {
                int mt0 = h*8 + mi*2;
                uint4 A0h = ph[((mt0    )*4 + ks)*32 + lane];
                uint4 A1h = ph[((mt0 + 1)*4 + ks)*32 + lane];
                uint4 A0l = pl[((mt0    )*4 + ks)*32 + lane];
                uint4 A1l = pl[((mt0 + 1)*4 + ks)*32 + lane];
                #pragma unroll
                for (int p = 0; p < 2; p++) {
                    uint32_t bh[4], bl[4];
                    ldB(bh, sb, L2_AH, 72, n0 + p*16, ks*16, lane);
                    ldB(bl, sb, L2_AL, 72, n0 + p*16, ks*16, lane);
                    #pragma unroll
                    for (int q = 0; q < 2; q++) {
                        int nt = p*2 + q;
                        mma16816(acc2[0][nt], (const uint32_t*)&A0h, &bh[q*2]);
                        mma16816(acc2[0][nt], (const uint32_t*)&A0h, &bl[q*2]);
                        mma16816(acc2[0][nt], (const uint32_t*)&A0l, &bh[q*2]);
                        mma16816(acc2[1][nt], (const uint32_t*)&A1h, &bh[q*2]);
                        mma16816(acc2[1][nt], (const uint32_t*)&A1h, &bl[q*2]);
                        mma16816(acc2[1][nt], (const uint32_t*)&A1l, &bh[q*2]);
                    }
                }
            }
            #pragma unroll
            for (int mt = 0; mt < 2; mt++)
                #pragma unroll
                for (int r = 0; r < 2; r++) {
                    int o = h*128 + m0 + mt*16 + r*8 + g;
                    float bv = skip_b[layer*SSC + o];
                    float* p = skip_g + ((size_t)b*SSC + o)*TT + t0;
                    #pragma unroll
                    for (int nt = 0; nt < 4; nt++) {
                        int tc = n0 + nt*8 + 2*tg;
                        float2 rv = make_float2(acc2[mt][nt][r*2+0] + bv,
                                                acc2[mt][nt][r*2+1] + bv);
                        if (!first) {
                            float2 old = *(const float2*)(p + tc);
                            rv.x += old.x; rv.y += old.y;
                        }
                        *(float2*)(p + tc) = rv;
                    }
                }
        }
    }

    // ---- GEMM3: res (M=64, K=64), 3-pass; residual x update
    if (!last) {
        const int mi3 = wid >> 2, ni3 = wid & 3;
        const int m0r = mi3 * 32, n0r = ni3 * 16;
        const uint4* ph = wr_h + (size_t)layer * 512;
        const uint4* pl = wr_l + (size_t)layer * 512;
        float acc3[2][2][4] = {};
        for (int ks = 0; ks < 4; ks++) {
            uint4 A0h = ph[((mi3*2    )*4 + ks)*32 + lane];
            uint4 A1h = ph[((mi3*2 + 1)*4 + ks)*32 + lane];
            uint4 A0l = pl[((mi3*2    )*4 + ks)*32 + lane];
            uint4 A1l = pl[((mi3*2 + 1)*4 + ks)*32 + lane];
            uint32_t bh[4], bl[4];
            ldB(bh, sb, L2_AH, 72, n0r, ks*16, lane);
            ldB(bl, sb, L2_AL, 72, n0r, ks*16, lane);
            #pragma unroll
            for (int q = 0; q < 2; q++) {
                mma16816(acc3[0][q], (const uint32_t*)&A0h, &bh[q*2]);
                mma16816(acc3[0][q], (const uint32_t*)&A0h, &bl[q*2]);
                mma16816(acc3[0][q], (const uint32_t*)&A0l, &bh[q*2]);
                mma16816(acc3[1][q], (const uint32_t*)&A1h, &bh[q*2]);
                mma16816(acc3[1][q], (const uint32_t*)&A1h, &bl[q*2]);
                mma16816(acc3[1][q], (const uint32_t*)&A1l, &bh[q*2]);
            }
        }
        #pragma unroll
        for (int mt = 0; mt < 2; mt++)
            #pragma unroll
            for (int r = 0; r < 2; r++) {
                int o = m0r + mt*16 + r*8 + g;
                float rb = res_b[layer*RRC + o];
                const float* xi = x_in  + ((size_t)b*RRC + o)*TT + t0;
                float*       xo = x_out + ((size_t)b*RRC + o)*TT + t0;
                #pragma unroll
                for (int nt = 0; nt < 2; nt++) {
                    int tc = n0r + nt*8 + 2*tg;
                    float2 xv = *(const float2*)(xi + tc);
                    float2 rv;
                    rv.x = (acc3[mt][nt][r*2+0] + rb + xv.x) * SQRT_HALF;
                    rv.y = (acc3[mt][nt][r*2+1] + rb + xv.y) * SQRT_HALF;
                    *(float2*)(xo + tc) = rv;
                }
            }
    }
}

// ===========================================================================
// final head (unchanged from R4)
// ===========================================================================
#define F_W 0
#define F_H 69632
#define F_SMEM 137216

__global__ void __launch_bounds__(512)
final_mma_kernel(const float* __restrict__ skip_g,
                 const float* __restrict__ Wout,
                 const float* __restrict__ Wend,
                 float* __restrict__ out)
{
    extern __shared__ char sb[];
    __half* W = (__half*)(sb + F_W);
    __half* H = (__half*)(sb + F_H);
    const int tid = threadIdx.x, wid = tid >> 5, lane = tid & 31;
    const int g = lane >> 2, tg = lane & 3;
    const int t0 = blockIdx.x * 128;
    const int b  = blockIdx.y;

    for (int e = tid; e < 32768; e += 512) {
        int t = e & 127, k = e >> 7;
        float v = skip_g[((size_t)b*SSC + k)*TT + t0 + t];
        H[t*264 + k] = __float2half_rn(fmaxf(v, 0.f));
    }

    const int mi = wid >> 1, ni = wid & 1;
    const int m0 = mi * 32, n0 = ni * 64;

    float acc[2][8][4] = {};
    for (int kc = 0; kc < 2; kc++) {
        __syncthreads();
        for (int e = tid; e < 32768; e += 512) {
            int o = e >> 7, kk = e & 127;
            W[o*136 + kk] = __float2half_rn(Wout[o*256 + kc*128 + kk]);
        }
        __syncthreads();
        for (int ks = 0; ks < 8; ks++) {
            int k0 = ks * 16;
            uint32_t ah[2][4];
            ldA(ah[0], sb, F_W, 136, m0,      k0, lane);
            ldA(ah[1], sb, F_W, 136, m0 + 16, k0, lane);
            #pragma unroll
            for (int p = 0; p < 4; p++) {
                uint32_t bh[4];
                ldB(bh, sb, F_H, 264, n0 + p*16, kc*128 + k0, lane);
                #pragma unroll
                for (int mt = 0; mt < 2; mt++)
                    #pragma unroll
                    for (int q = 0; q < 2; q++)
                        mma16816(acc[mt][p*2+q], ah[mt], &bh[q*2]);
            }
        }
    }
    __syncthreads();

    #pragma unroll
    for (int mt = 0; mt < 2; mt++)
        #pragma unroll
        for (int r = 0; r < 2; r++) {
            int o = m0 + mt*16 + r*8 + g;
            #pragma unroll
            for (int nt = 0; nt < 8; nt++) {
                int tc = n0 + nt*8 + 2*tg;
                H[tc*264 + o]       = __float2half_rn(fmaxf(acc[mt][nt][r*2+0], 0.f));
                H[(tc + 1)*264 + o] = __float2half_rn(fmaxf(acc[mt][nt][r*2+1], 0.f));
            }
        }
    __syncthreads();

    float acc2[2][8][4] = {};
    for (int kc = 0; kc < 2; kc++) {
        __syncthreads();
        for (int e = tid; e < 32768; e += 512) {
            int o = e >> 7, kk = e & 127;
            W[o*136 + kk] = __float2half_rn(Wend[o*256 + kc*128 + kk]);
        }
        __syncthreads();
        for (int ks = 0; ks < 8; ks++) {
            int k0 = ks * 16;
            uint32_t ah[2][4];
            ldA(ah[0], sb, F_W, 136, m0,      k0, lane);
            ldA(ah[1], sb, F_W, 136, m0 + 16, k0, lane);
            #pragma unroll
            for (int p = 0; p < 4; p++) {
                uint32_t bh[4];
                ldB(bh, sb, F_H, 264, n0 + p*16, kc*128 + k0, lane);
                #pragma unroll
                for (int mt = 0; mt < 2; mt++)
                    #pragma unroll
                    for (int q = 0; q < 2; q++)
                        mma16816(acc2[mt][p*2+q], ah[mt], &bh[q*2]);
            }
        }
    }

    #pragma unroll
    for (int mt = 0; mt < 2; mt++)
        #pragma unroll
        for (int r = 0; r < 2; r++) {
            int o = m0 + mt*16 + r*8 + g;
            float* op = out + ((size_t)b*256 + o)*TT;
            #pragma unroll
            for (int nt = 0; nt < 8; nt++) {
                int tc = t0 + n0 + nt*8 + 2*tg;
                if (tc + 1 < TT) op[tc + 1] = acc2[mt][nt][r*2+0];
                if (tc + 2 < TT) op[tc + 2] = acc2[mt][nt][r*2+1];
            }
        }
    if (blockIdx.x == 0 && tid < 256) out[((size_t)b*256 + tid)*TT] = 0.f;
}

// ===========================================================================
extern "C" void kernel_launch(void* const* d_in, const int* in_sizes, int n_in,
                              void* d_out, int out_size)
{
    const float* features   = (const float*)d_in[0];
    const int*   tokens     = (const int*)  d_in[1];
    const float* embed      = (const float*)d_in[2];
    const float* cond_W     = (const float*)d_in[3];
    const float* cond_b     = (const float*)d_in[4];
    const float* dilate_W   = (const float*)d_in[5];
    const float* dilate_b   = (const float*)d_in[6];
    const float* res_W      = (const float*)d_in[7];
    const float* res_b      = (const float*)d_in[8];
    const float* skip_W     = (const float*)d_in[9];
    const float* skip_b     = (const float*)d_in[10];
    const float* conv_out_W = (const float*)d_in[11];
    const float* conv_end_W = (const float*)d_in[12];
    float* outp = (float*)d_out;

    float* out_r   = outp;
    float* inact_r = outp + INACT_OFF;
    float* cond_r  = outp + COND_OFF;

    float *x0, *x1, *skip;
    uint4 *wdh, *wdl, *wsh, *wsl, *wrh, *wrl;
    cudaGetSymbolAddress((void**)&x0,   g_x0);
    cudaGetSymbolAddress((void**)&x1,   g_x1);
    cudaGetSymbolAddress((void**)&skip, g_skip);
    cudaGetSymbolAddress((void**)&wdh,  g_wd_h);
    cudaGetSymbolAddress((void**)&wdl,  g_wd_l);
    cudaGetSymbolAddress((void**)&wsh,  g_ws_h);
    cudaGetSymbolAddress((void**)&wsl,  g_ws_l);
    cudaGetSymbolAddress((void**)&wrh,  g_wr_h);
    cudaGetSymbolAddress((void**)&wrl,  g_wr_l);

    static const int DIL[LLC] = {1,2,4,8,16,32,64,128,256,1,2,4,8,16,32,64};

    cudaFuncSetAttribute(cond_mma_kernel,   cudaFuncAttributeMaxDynamicSharedMemorySize, CO_SMEM);
    cudaFuncSetAttribute(layer_mma2_kernel, cudaFuncAttributeMaxDynamicSharedMemorySize, L2_SMEM);
    cudaFuncSetAttribute(final_mma_kernel,  cudaFuncAttributeMaxDynamicSharedMemorySize, F_SMEM);

    pack_dilate<<<128, 256>>>(dilate_W, wdh, wdl);
    pack_skip<<<128, 256>>>(skip_W, wsh, wsl);
    pack_res<<<30, 256>>>(res_W, wrh, wrl);

    embed_kernel<<<dim3(TT/256, BB), 256>>>(tokens, embed, x0);
    cond_mma_kernel<<<dim3(TT/128, LLC, BB), 512, CO_SMEM>>>(features, cond_W, cond_b, cond_r);

    float* xi = x0;
    float* xo = x1;
    for (int i = 0; i < LLC; i++) {
        layer_mma2_kernel<<<dim3(TT/64, BB), 256, L2_SMEM>>>(
            xi, xo, wdh, wdl, dilate_b, wrh, wrl, res_b, wsh, wsl, skip_b,
            cond_r, inact_r, skip,
            i, DIL[i], (i == 0) ? 1 : 0, (i == LLC-1) ? 1 : 0);
        float* t = xi; xi = xo; xo = t;
    }

    final_mma_kernel<<<dim3(TT/128, BB), 512, F_SMEM>>>(skip, conv_out_W, conv_end_W, out_r);
}